// round 16
// baseline (speedup 1.0000x reference)
#include <cuda_runtime.h>
#include <stdint.h>

// PluginEmbedding: sparse embedding lookup + per-row sum combine.
//   d_in[0] table         float32 [1000000, 128]
//   d_in[1] row_offsets   int32   [212993]
//   d_in[2] value_tensors int32   [212992]
// Output: float32 [212992, 128]
//
// R15 showed TMA-for-gather loses (bulk-sync latency exposure), but left the
// write path untested. Hypothesis: R10's ~60% DRAM ceiling is shared L1tex
// wavefront/miss capacity, half consumed by the 109MB STG stream. This
// version keeps the R10 LDG gather engine (batch-4 independent 512B gathers
// off SMEM metadata) but routes ALL output through one contiguous 32KB
// cp.async.bulk store per block -> zero STG wavefronts in L1tex.

static constexpr int  kVocab        = 1000000;
static constexpr long long kNumRows = 8192LL * 26LL; // 212992
static constexpr int  kRowsPerBlock = 64;            // 3328 blocks (exact)
static constexpr int  kRowBytes     = 512;
static constexpr int  kBatch        = 4;

static constexpr int  kBufBytes  = kRowsPerBlock * kRowBytes;        // 32768
static constexpr int  kMetaOff   = kBufBytes;
static constexpr int  kSmemTotal = kMetaOff + 3 * kRowsPerBlock * 4; // 33536

__device__ __forceinline__ unsigned smem_u32(const void* p) {
    unsigned a;
    asm("{ .reg .u64 t; cvta.to.shared.u64 t, %1; cvt.u32.u64 %0, t; }"
        : "=r"(a) : "l"(p));
    return a;
}

__global__ __launch_bounds__(256) void pe_gather_hybrid_kernel(
    const float* __restrict__ table,
    const int*   __restrict__ row_offsets,
    const int*   __restrict__ vals,
    float*       __restrict__ out)
{
    extern __shared__ char smem[];
    float4* buf   = reinterpret_cast<float4*>(smem);
    int*    s_beg = reinterpret_cast<int*>(smem + kMetaOff);
    int*    s_end = s_beg + kRowsPerBlock;
    int*    s_idx = s_end + kRowsPerBlock;

    const int t = threadIdx.x;
    const unsigned blockRow0 = blockIdx.x * kRowsPerBlock;

    // Phase A: coalesced metadata stage (threads 0..63).
    if (t < kRowsPerBlock) {
        const int b = __ldg(&row_offsets[blockRow0 + t]);
        const int e = __ldg(&row_offsets[blockRow0 + t + 1]);
        s_beg[t] = b;
        s_end[t] = e;
        s_idx[t] = (b < e) ? __ldg(&vals[b]) : -1;
    }
    __syncthreads();

    const int warp = t >> 5;
    const int lane = t & 31;
    const char* tbl = reinterpret_cast<const char*>(table);
    const unsigned laneOff = (unsigned)lane * 16u;

    // Phase B: warp owns 8 rows -> 2 batches of 4 independent 512B gathers.
    // Results go to SMEM (not STG) — the write stream leaves L1tex entirely.
#pragma unroll
    for (int batch = 0; batch < 2; ++batch) {
        const int base = warp * 8 + batch * kBatch;

        int idx[kBatch];
#pragma unroll
        for (int u = 0; u < kBatch; ++u) idx[u] = s_idx[base + u];  // LDS bcast

        float4 v[kBatch];
#pragma unroll
        for (int u = 0; u < kBatch; ++u) {
            const unsigned i = (unsigned)((idx[u] >= 0) ? min(idx[u], kVocab - 1) : 0);
            v[u] = __ldg(reinterpret_cast<const float4*>(
                       tbl + i * (unsigned)kRowBytes + laneOff));
        }

#pragma unroll
        for (int u = 0; u < kBatch; ++u) {
            const int r = base + u;
            float4 acc = (idx[u] >= 0) ? v[u] : make_float4(0.f, 0.f, 0.f, 0.f);
            // Generic nnz>1 tail (absent in this dataset, kept for correctness).
            const int e = s_end[r];
            for (int j = s_beg[r] + 1; j < e; ++j) {
                int i = __ldg(&vals[j]);
                i = min(max(i, 0), kVocab - 1);
                const float4 tt = __ldg(reinterpret_cast<const float4*>(
                                      tbl + (unsigned)i * (unsigned)kRowBytes + laneOff));
                acc.x += tt.x; acc.y += tt.y; acc.z += tt.z; acc.w += tt.w;
            }
            buf[r * 32 + lane] = acc;   // STS, conflict-free (stride 512B)
        }
    }

    __syncthreads();
    asm volatile("fence.proxy.async.shared::cta;" ::: "memory");

    // One contiguous 32KB TMA bulk store for the block's 64 output rows.
    // Only thread 0 issues+waits; the other 7 warps exit and the tail
    // overlaps with the 5 other resident blocks on this SM.
    if (t == 0) {
        char* dst = reinterpret_cast<char*>(out) +
                    (unsigned long long)blockRow0 * kRowBytes;
        asm volatile(
            "cp.async.bulk.global.shared::cta.bulk_group [%0], [%1], %2;"
            :: "l"(dst), "r"(smem_u32(smem)), "r"((unsigned)kBufBytes)
            : "memory");
        asm volatile("cp.async.bulk.commit_group;" ::: "memory");
        asm volatile("cp.async.bulk.wait_group 0;" ::: "memory");
    }
}

extern "C" void kernel_launch(void* const* d_in, const int* in_sizes, int n_in,
                              void* d_out, int out_size)
{
    const float* table = (const float*)d_in[0];
    const int*   offs  = (const int*)d_in[1];
    const int*   vals  = (const int*)d_in[2];
    float*       out   = (float*)d_out;

    (void)in_sizes; (void)n_in; (void)out_size;

    const int block = 256;
    const unsigned grid = (unsigned)(kNumRows / kRowsPerBlock);   // 3328

    pe_gather_hybrid_kernel<<<grid, block, kSmemTotal>>>(table, offs, vals, out);
}

// round 17
// speedup vs baseline: 1.0759x; 1.0759x over previous
#include <cuda_runtime.h>
#include <stdint.h>

// PluginEmbedding: sparse embedding lookup + per-row sum combine.
//   d_in[0] table         float32 [1000000, 128]
//   d_in[1] row_offsets   int32   [212993]
//   d_in[2] value_tensors int32   [212992]
// Output: float32 [212992, 128]
//
// Series conclusion: ~60% DRAM / ~32.5us plateau is DRAM-side; R10's LDG
// batch-4 engine is the best read path (TMA gather R15 and TMA store R16
// both falsified alternative ceilings). Last mechanism: L2 write-allocation.
// The 109MB output stream (.cs still ALLOCATES) evicts table lines, capping
// cross-replay table residency at ~50% (47MB read misses). This round: R10
// verbatim but stores via __stwt (st.global.wt, write-through) -> if wt
// skips L2 allocation, table residency rises and read misses collapse.

static constexpr int  kVocab        = 1000000;
static constexpr long long kNumRows = 8192LL * 26LL; // 212992
static constexpr int  kRowsPerBlock = 128;           // 1664 blocks (exact)
static constexpr int  kBatch        = 4;             // gathers in flight / warp
static constexpr int  kRowBytes     = 512;           // 128 floats

__global__ __launch_bounds__(256, 6) void pe_gather_kernel(
    const float* __restrict__ table,
    const int*   __restrict__ row_offsets,
    const int*   __restrict__ vals,
    float*       __restrict__ out)
{
    __shared__ int s_idx[kRowsPerBlock];
    __shared__ int s_beg[kRowsPerBlock];
    __shared__ int s_end[kRowsPerBlock];

    const int t = threadIdx.x;
    const unsigned blockRow0 = blockIdx.x * kRowsPerBlock;

    // Phase A: coalesced metadata stage (once per block, overlapped across
    // the ~6 resident blocks per SM).
    if (t < kRowsPerBlock) {
        const int b = __ldg(&row_offsets[blockRow0 + t]);
        const int e = __ldg(&row_offsets[blockRow0 + t + 1]);
        s_beg[t] = b;
        s_end[t] = e;
        s_idx[t] = (b < e) ? __ldg(&vals[b]) : -1;
    }
    __syncthreads();

    const int warp = t >> 5;
    const int lane = t & 31;
    const char* tbl = reinterpret_cast<const char*>(table);
    char*       o   = reinterpret_cast<char*>(out);
    const unsigned laneOff = (unsigned)lane * 16u;

    // Phase B: warp owns 16 rows -> 4 batches of 4 independent 512B gathers.
#pragma unroll
    for (int batch = 0; batch < 4; ++batch) {
        const int base = warp * 16 + batch * kBatch;

        int idx[kBatch];
#pragma unroll
        for (int u = 0; u < kBatch; ++u) idx[u] = s_idx[base + u];  // LDS bcast

        // 4 independent 512B gathers — the only DRAM-latency ops in the loop.
        float4 v[kBatch];
#pragma unroll
        for (int u = 0; u < kBatch; ++u) {
            const unsigned i = (unsigned)((idx[u] >= 0) ? min(idx[u], kVocab - 1) : 0);
            v[u] = __ldg(reinterpret_cast<const float4*>(
                       tbl + i * (unsigned)kRowBytes + laneOff));
        }

#pragma unroll
        for (int u = 0; u < kBatch; ++u) {
            float4 acc = (idx[u] >= 0) ? v[u] : make_float4(0.f, 0.f, 0.f, 0.f);
            // Generic nnz>1 tail (absent in this dataset, kept for correctness).
            const int e = s_end[base + u];
            for (int j = s_beg[base + u] + 1; j < e; ++j) {
                int i = __ldg(&vals[j]);
                i = min(max(i, 0), kVocab - 1);
                const float4 tt = __ldg(reinterpret_cast<const float4*>(
                                      tbl + (unsigned)i * (unsigned)kRowBytes + laneOff));
                acc.x += tt.x; acc.y += tt.y; acc.z += tt.z; acc.w += tt.w;
            }
            const unsigned row = blockRow0 + (unsigned)(base + u);
            // Write-through store: keep the output stream from allocating L2,
            // preserving table residency across graph replays.
            __stwt(reinterpret_cast<float4*>(
                       o + row * (unsigned)kRowBytes + laneOff), acc);
        }
    }
}

extern "C" void kernel_launch(void* const* d_in, const int* in_sizes, int n_in,
                              void* d_out, int out_size)
{
    const float* table = (const float*)d_in[0];
    const int*   offs  = (const int*)d_in[1];
    const int*   vals  = (const int*)d_in[2];
    float*       out   = (float*)d_out;

    (void)in_sizes; (void)n_in; (void)out_size;

    const int block = 256;
    const unsigned grid = (unsigned)(kNumRows / kRowsPerBlock);   // 1664

    pe_gather_kernel<<<grid, block>>>(table, offs, vals, out);
}